// round 16
// baseline (speedup 1.0000x reference)
#include <cuda_runtime.h>
#include <cstdint>

#define NN 8192
#define DD 64
#define KK 8
#define LL 17
#define DIN 128
#define EPS 1e-5f
#define R9 9             // nonzero h_input rows
#define R12 12           // rows needing full compute

// ---------------- device scratch ----------------
__device__ float g_hflat[NN*KK*DD];       // [N,8,64] sorted mailbox
__device__ float g_y[NN*R12*DD];          // [N,12,64]
__device__ float g_yc[DD];                // constant tail row (l=12..16)
__device__ float g_bnsum[DD];
__device__ float g_bnsq[DD];
__device__ float g_w1q[64*256];           // fc1_w quad-interleaved: [k][u][{x0,x1,z0,z1}]
__device__ float g_w2t[128*64];           // fc2_w^T [c][d]

__device__ __forceinline__ float sigm(float x) { return 1.f/(1.f+__expf(-x)); }

// smem float offsets (k3): h [4][9][64] | g [4][12][128] | ob [4][12][64] | rr | bnp | src
#define FO_H   0         // 2304
#define FO_G   2304      // 6144
#define FO_OB  8448      // 3072
#define FO_RR  11520     // 48
#define FO_BNP 11568     // 512
#define FO_SRC 12080     // 32
#define SMEM3  (12112*4) // 48448 B

// ---------------- KW: weight prep (+ zero BN accumulators) ----------------
__global__ void kw(const float* __restrict__ fc1w, const float* __restrict__ fc2w) {
    int i = blockIdx.x*256 + threadIdx.x;      // grid 64
    if (blockIdx.x == 0 && threadIdx.x < DD) { g_bnsum[threadIdx.x] = 0.f; g_bnsq[threadIdx.x] = 0.f; }
    {
        int c = i >> 6, k = i & 63;
        int u, j;
        if (c < DIN) { u = c >> 1; j = c & 1; }
        else         { u = (c - DIN) >> 1; j = 2 + (c & 1); }
        g_w1q[k*256 + u*4 + j] = fc1w[i];
    }
    if (i < 64*128) { int d = i >> 7, c = i & 127; g_w2t[c*64 + d] = fc2w[i]; }
}

// ---------------- KC: constant tail row yc (rows 12..16) ----------------
__global__ void kc(const float* __restrict__ fc1b, const float* __restrict__ convw,
                   const float* __restrict__ convb, const float* __restrict__ fc2w,
                   const float* __restrict__ fc2b, const float* __restrict__ rmsw) {
    __shared__ float gc[128];
    __shared__ float oc[64];
    int t = threadIdx.x;   // 128
    {
        float cwsum = convw[t*4] + convw[t*4+1] + convw[t*4+2] + convw[t*4+3];
        float xc = convb[t] + fc1b[t]*cwsum;
        float z = fc1b[DIN + t];
        gc[t] = xc*sigm(xc) * (z*sigm(z));
    }
    __syncthreads();
    if (t < 64) {
        float s = fc2b[t];
        for (int c = 0; c < 128; c++) s += fc2w[t*128 + c]*gc[c];
        oc[t] = s;
    }
    __syncthreads();
    if (t < 64) {
        float ss = 0.f;
        for (int d = 0; d < 64; d++) ss += oc[d]*oc[d];
        g_yc[t] = oc[t] * rsqrtf(ss*(1.f/DD) + EPS) * rmsw[t];
    }
}

// ---------------- K1: message + mailbox rank-sort, 1 (k, d4) per thread ----------------
__global__ void k1(const float* __restrict__ hs, const float* __restrict__ hs_e,
                   const float* __restrict__ degree, const float* __restrict__ noise) {
    int n = blockIdx.x;
    int t = threadIdx.x;        // 128
    int k = t >> 4, d4 = t & 15;
    float deg = __ldg(&degree[n]);
    float sc[KK];
#pragma unroll
    for (int j = 0; j < KK; j++) sc[j] = deg + __ldg(&noise[n*KK + j]);
    float myk = sc[k];
    int r = 0;
#pragma unroll
    for (int j = 0; j < KK; j++)
        r += (sc[j] < myk) || (sc[j] == myk && j < k);   // stable rank
    float4 h4 = ((const float4*)(hs + n*DD))[d4];
    float4 e4 = ((const float4*)(hs_e + (size_t)(n*KK + k)*DD))[d4];
    float4 m;
    m.x = h4.x * sigm(e4.x);
    m.y = h4.y * sigm(e4.y);
    m.z = h4.z * sigm(e4.z);
    m.w = h4.w * sigm(e4.w);
    ((float4*)(g_hflat + (size_t)n*(KK*DD) + r*DD))[d4] = m;
}

// ---------------- K3: gather + GatedCNN, 4 nodes/CTA, conv in registers ----------------
// 2048 CTAs x 256 threads, TARGET 4 CTAs/SM (ptxas spills cold epilogue state).
// fc1: 64 thr/node, thread owns channels {2u,2u+1,128+2u,128+2u+1} x 9 rows;
//      conv+gate computed in registers, only gated G written to smem.
// fc2: 64 thr/node, 1 d x 12 rows.
__global__ void __launch_bounds__(256, 4)
k3(const float* __restrict__ hs, const int* __restrict__ src,
   const float* __restrict__ fc1b, const float* __restrict__ convw,
   const float* __restrict__ convb, const float* __restrict__ fc2b,
   const float* __restrict__ rmsw) {
    extern __shared__ float sm[];
    float* h    = sm + FO_H;     // [4 nd][9 l][64 k]
    float* gbuf = sm + FO_G;     // [4 nd][12 l][128 c]
    float* ob   = sm + FO_OB;    // [4 nd][12 l][64 d]
    float* rr   = sm + FO_RR;    // [48]
    float* bnp  = sm + FO_BNP;   // [512]
    int*   ssrc = (int*)(sm + FO_SRC);   // [32]

    int t = threadIdx.x;
    int n0 = blockIdx.x*4;
    int nd = t >> 6, u = t & 63;

    // ---- stage src indices + h row 0 (= hs) ----
    if (t < 32) ssrc[t] = __ldg(&src[n0*KK + t]);
    h[nd*(R9*DD) + u] = __ldg(&hs[(size_t)(n0 + nd)*DD + u]);
    __syncthreads();

    // ---- gather (A+I) spmm: rows 1..8 = own mailbox + 8 src mailboxes ----
#pragma unroll
    for (int i = t; i < 4*128; i += 256) {
        int gn = i >> 7, idx = i & 127;
        float4 a4 = ((const float4*)(g_hflat + (size_t)(n0 + gn)*(KK*DD)))[idx];
#pragma unroll
        for (int k = 0; k < KK; k++) {
            int s = ssrc[gn*KK + k];
            float4 v = ((const float4*)(g_hflat + (size_t)s*(KK*DD)))[idx];
            a4.x += v.x; a4.y += v.y; a4.z += v.z; a4.w += v.w;
        }
        ((float4*)(h + gn*(R9*DD) + DD))[idx] = a4;
    }
    __syncthreads();

    // ---- fc1 (channels {2u,2u+1,128+2u,128+2u+1}) + in-register conv + gate ----
    {
        float acc[R9][4];
#pragma unroll
        for (int l = 0; l < R9; l++) { acc[l][0]=0; acc[l][1]=0; acc[l][2]=0; acc[l][3]=0; }
        const float* hrow = h + nd*(R9*DD);
#pragma unroll 2
        for (int k4 = 0; k4 < 16; k4++) {
            float4 w0 = *(const float4*)&g_w1q[(k4*4+0)*256 + 4*u];
            float4 w1 = *(const float4*)&g_w1q[(k4*4+1)*256 + 4*u];
            float4 w2 = *(const float4*)&g_w1q[(k4*4+2)*256 + 4*u];
            float4 w3 = *(const float4*)&g_w1q[(k4*4+3)*256 + 4*u];
#pragma unroll
            for (int l = 0; l < R9; l++) {
                float4 h4 = *(const float4*)&hrow[l*DD + k4*4];
                acc[l][0] += h4.x*w0.x + h4.y*w1.x + h4.z*w2.x + h4.w*w3.x;
                acc[l][1] += h4.x*w0.y + h4.y*w1.y + h4.z*w2.y + h4.w*w3.y;
                acc[l][2] += h4.x*w0.z + h4.y*w1.z + h4.z*w2.z + h4.w*w3.z;
                acc[l][3] += h4.x*w0.w + h4.y*w1.w + h4.z*w2.w + h4.w*w3.w;
            }
        }
        int c0 = 2*u, c1 = 2*u + 1;
        float b1x0 = __ldg(&fc1b[c0]),       b1x1 = __ldg(&fc1b[c1]);
        float b1z0 = __ldg(&fc1b[DIN + c0]), b1z1 = __ldg(&fc1b[DIN + c1]);
        float4 cwa = *(const float4*)&convw[c0*4];   // {w0,w1,w2,w3} ch c0
        float4 cwb = *(const float4*)&convw[c1*4];
        float cba = __ldg(&convb[c0]), cbb = __ldg(&convb[c1]);
        float* grow = gbuf + nd*(R12*DIN);
        float am1 = 0.f, am2 = 0.f, am3 = 0.f;   // history ch c0
        float bm1 = 0.f, bm2 = 0.f, bm3 = 0.f;   // history ch c1
#pragma unroll
        for (int l = 0; l < R12; l++) {
            float xa = (l <= 8) ? (acc[l][0] + b1x0) : b1x0;
            float xb = (l <= 8) ? (acc[l][1] + b1x1) : b1x1;
            float xca = cba + xa*cwa.w + am1*cwa.z + am2*cwa.y + am3*cwa.x;
            float xcb = cbb + xb*cwb.w + bm1*cwb.z + bm2*cwb.y + bm3*cwb.x;
            am3 = am2; am2 = am1; am1 = xa;
            bm3 = bm2; bm2 = bm1; bm1 = xb;
            float za = (l <= 8) ? (acc[l][2] + b1z0) : b1z0;
            float zb = (l <= 8) ? (acc[l][3] + b1z1) : b1z1;
            float2 gv;
            gv.x = xca*sigm(xca) * (za*sigm(za));
            gv.y = xcb*sigm(xcb) * (zb*sigm(zb));
            *(float2*)&grow[l*DIN + c0] = gv;
        }
    }
    __syncthreads();

    // ---- fc2: nd, d = u, all 12 rows ----
    {
        int d = u;
        float acc2[R12];
#pragma unroll
        for (int j = 0; j < R12; j++) acc2[j] = 0.f;
        const float* grow = gbuf + nd*(R12*DIN);
#pragma unroll 2
        for (int c4 = 0; c4 < 32; c4++) {
            float wa = __ldg(&g_w2t[(c4*4+0)*64 + d]);
            float wb = __ldg(&g_w2t[(c4*4+1)*64 + d]);
            float wc = __ldg(&g_w2t[(c4*4+2)*64 + d]);
            float wd = __ldg(&g_w2t[(c4*4+3)*64 + d]);
#pragma unroll
            for (int j = 0; j < R12; j++) {
                float4 g4 = *(const float4*)&grow[j*DIN + c4*4];
                acc2[j] += g4.x*wa + g4.y*wb + g4.z*wc + g4.w*wd;
            }
        }
        float b2 = __ldg(&fc2b[d]);
        float* obrow = ob + nd*(R12*DD);
#pragma unroll
        for (int j = 0; j < R12; j++) obrow[j*DD + d] = acc2[j] + b2;
    }
    __syncthreads();

    // ---- rms per row (48 rows, staggered reads) ----
    if (t < 4*R12) {
        int nn_ = t / R12, l = t % R12;
        const float* row = ob + nn_*(R12*DD) + l*DD;
        float s = 0.f;
#pragma unroll
        for (int dd = 0; dd < DD; dd++) { float v = row[(dd + t) & 63]; s += v*v; }
        rr[t] = rsqrtf(s * (1.f/DD) + EPS);
    }
    __syncthreads();

    // ---- y = rmsnorm*rms_w + h_input (rows>8: residual 0); BN partials ----
    {
        int d = u;
        float rw = __ldg(&rmsw[d]);
        float bsum = 0.f, bsq = 0.f;
        float* ydst = g_y + (size_t)(n0 + nd)*(R12*DD);
        const float* hrow = h + nd*(R9*DD);
        const float* obrow = ob + nd*(R12*DD);
#pragma unroll
        for (int l = 0; l < R12; l++) {
            float res = (l <= 8) ? hrow[l*DD + d] : 0.f;
            float v = obrow[l*DD + d] * rr[nd*R12 + l] * rw + res;
            ydst[l*DD + d] = v;
            bsum += v; bsq += v*v;
        }
        bnp[t] = bsum; bnp[256 + t] = bsq;
    }
    __syncthreads();
    if (t < DD) {
        atomicAdd(&g_bnsum[t], bnp[t] + bnp[t+64] + bnp[t+128] + bnp[t+192]);
    } else if (t < 2*DD) {
        int d = t - DD;
        atomicAdd(&g_bnsq[d], bnp[256+d] + bnp[256+d+64] + bnp[256+d+128] + bnp[256+d+192]);
    }
}

// ---------------- K5: BN apply + ReLU6 + L-agg (12 rows + constant tail) ----------------
__global__ void k5(const float* __restrict__ hs, const float* __restrict__ gamma,
                   const float* __restrict__ beta, const float* __restrict__ aggw,
                   const float* __restrict__ aggb, float* __restrict__ out) {
    int idx = blockIdx.x*256 + threadIdx.x;
    int d = idx & 63;
    float cnt = (float)(NN*LL);
    float yc = g_yc[d];
    float bs = g_bnsum[d] + 5.f*NN*yc;
    float bq = g_bnsq[d]  + 5.f*NN*yc*yc;
    float mean = bs / cnt;
    float var  = bq / cnt - mean*mean;
    float is = rsqrtf(var + EPS);
    float ga = __ldg(&gamma[d]) * is;
    float be = __ldg(&beta[d]) - mean * ga;
    const float* yrow = g_y + (size_t)(idx >> 6)*(R12*DD);
    float s = __ldg(&aggb[0]);
#pragma unroll
    for (int l = 0; l < R12; l++) {
        float v = yrow[l*DD + d] * ga + be;
        v = fminf(fmaxf(v, 0.f), 6.f);
        s += v * __ldg(&aggw[l]);
    }
    {
        float vc = fminf(fmaxf(yc * ga + be, 0.f), 6.f);
        float tailw = __ldg(&aggw[12]) + __ldg(&aggw[13]) + __ldg(&aggw[14])
                    + __ldg(&aggw[15]) + __ldg(&aggw[16]);
        s += vc * tailw;
    }
    out[idx] = s + hs[idx];
}

// ---------------- host ----------------
extern "C" void kernel_launch(void* const* d_in, const int* in_sizes, int n_in,
                              void* d_out, int out_size) {
    const float* hs     = (const float*)d_in[0];
    const float* hs_e   = (const float*)d_in[1];
    const float* degree = (const float*)d_in[2];
    const float* noise  = (const float*)d_in[3];
    const float* fc1w   = (const float*)d_in[4];
    const float* fc1b   = (const float*)d_in[5];
    const float* convw  = (const float*)d_in[6];
    const float* convb  = (const float*)d_in[7];
    const float* fc2w   = (const float*)d_in[8];
    const float* fc2b   = (const float*)d_in[9];
    const float* rmsw   = (const float*)d_in[10];
    const float* gamma  = (const float*)d_in[11];
    const float* beta   = (const float*)d_in[12];
    const float* aggw   = (const float*)d_in[13];
    const float* aggb   = (const float*)d_in[14];
    const int*   src    = (const int*)d_in[15];
    float* out = (float*)d_out;

    cudaFuncSetAttribute(k3, cudaFuncAttributeMaxDynamicSharedMemorySize, SMEM3);

    kw<<<64, 256>>>(fc1w, fc2w);
    kc<<<1, 128>>>(fc1b, convw, convb, fc2w, fc2b, rmsw);
    k1<<<NN, 128>>>(hs, hs_e, degree, noise);
    k3<<<NN/4, 256, SMEM3>>>(hs, src, fc1b, convw, convb, fc2b, rmsw);
    k5<<<NN*DD/256, 256>>>(hs, gamma, beta, aggw, aggb, out);
}

// round 17
// speedup vs baseline: 1.1111x; 1.1111x over previous
#include <cuda_runtime.h>
#include <cstdint>

#define NN 8192
#define DD 64
#define KK 8
#define LL 17
#define DIN 128
#define EPS 1e-5f
#define R9 9             // nonzero h_input rows
#define R12 12           // rows needing full compute

// ---------------- device scratch ----------------
__device__ float g_hflat[NN*KK*DD];       // [N,8,64] sorted mailbox
__device__ float g_y[NN*R12*DD];          // [N,12,64]
__device__ float g_yc[DD];                // constant tail row (l=12..16)
__device__ float g_bnsum[DD];
__device__ float g_bnsq[DD];
__device__ float g_w1q[64*256];           // fc1_w quad-interleaved: [k][u][{x0,x1,z0,z1}]
__device__ float g_w2t[128*64];           // fc2_w^T [c][d]

__device__ __forceinline__ float sigm(float x) { return 1.f/(1.f+__expf(-x)); }

// smem float offsets (k3): h [4][9][64] | g [4][12][128] | ob [4][12][64] | rr | bnp
#define FO_H   0         // 2304
#define FO_G   2304      // 6144
#define FO_OB  8448      // 3072
#define FO_RR  11520     // 48
#define FO_BNP 11568     // 512
#define SMEM3  (12080*4) // 48320 B

// ---------------- KWC: weight prep + BN zero + constant tail row ----------------
__global__ void kwc(const float* __restrict__ fc1w, const float* __restrict__ fc2w,
                    const float* __restrict__ fc1b, const float* __restrict__ convw,
                    const float* __restrict__ convb, const float* __restrict__ fc2b,
                    const float* __restrict__ rmsw) {
    int b = blockIdx.x;
    int t = threadIdx.x;
    if (b < 64) {
        int i = b*256 + t;
        if (b == 0 && t < DD) { g_bnsum[t] = 0.f; g_bnsq[t] = 0.f; }
        {
            int c = i >> 6, k = i & 63;
            int u, j;
            if (c < DIN) { u = c >> 1; j = c & 1; }
            else         { u = (c - DIN) >> 1; j = 2 + (c & 1); }
            g_w1q[k*256 + u*4 + j] = fc1w[i];
        }
        if (i < 64*128) { int d = i >> 7, c = i & 127; g_w2t[c*64 + d] = fc2w[i]; }
    } else {
        // constant tail row yc (rows 12..16); reads fc2w row-major (indep of transpose)
        __shared__ float gc[128];
        __shared__ float oc[64];
        if (t < 128) {
            float cwsum = convw[t*4] + convw[t*4+1] + convw[t*4+2] + convw[t*4+3];
            float xc = convb[t] + fc1b[t]*cwsum;
            float z = fc1b[DIN + t];
            gc[t] = xc*sigm(xc) * (z*sigm(z));
        }
        __syncthreads();
        if (t < 64) {
            float s = fc2b[t];
            for (int c = 0; c < 128; c++) s += fc2w[t*128 + c]*gc[c];
            oc[t] = s;
        }
        __syncthreads();
        if (t < 64) {
            float ss = 0.f;
            for (int d = 0; d < 64; d++) ss += oc[d]*oc[d];
            g_yc[t] = oc[t] * rsqrtf(ss*(1.f/DD) + EPS) * rmsw[t];
        }
    }
}

// ---------------- K1: message + mailbox rank-sort, 4 nodes/block ----------------
__global__ void k1(const float* __restrict__ hs, const float* __restrict__ hs_e,
                   const float* __restrict__ degree, const float* __restrict__ noise) {
    int t = threadIdx.x;        // 512
    int n = blockIdx.x*4 + (t >> 7);
    int g = t & 127;
    int k = g >> 4, d4 = g & 15;
    float deg = __ldg(&degree[n]);
    float sc[KK];
#pragma unroll
    for (int j = 0; j < KK; j++) sc[j] = deg + __ldg(&noise[n*KK + j]);
    float myk = sc[k];
    int r = 0;
#pragma unroll
    for (int j = 0; j < KK; j++)
        r += (sc[j] < myk) || (sc[j] == myk && j < k);   // stable rank
    float4 h4 = ((const float4*)(hs + n*DD))[d4];
    float4 e4 = ((const float4*)(hs_e + (size_t)(n*KK + k)*DD))[d4];
    float4 m;
    m.x = h4.x * sigm(e4.x);
    m.y = h4.y * sigm(e4.y);
    m.z = h4.z * sigm(e4.z);
    m.w = h4.w * sigm(e4.w);
    ((float4*)(g_hflat + (size_t)n*(KK*DD) + r*DD))[d4] = m;
}

// ---------------- K3: gather + GatedCNN, 4 nodes/CTA, conv in registers ----------------
// 2048 CTAs x 256 threads, 3 CTAs/SM (R14-proven shape).
__global__ void __launch_bounds__(256, 3)
k3(const float* __restrict__ hs, const int* __restrict__ src,
   const float* __restrict__ fc1b, const float* __restrict__ convw,
   const float* __restrict__ convb, const float* __restrict__ fc2b,
   const float* __restrict__ rmsw) {
    extern __shared__ float sm[];
    float* h    = sm + FO_H;     // [4 nd][9 l][64 k]
    float* gbuf = sm + FO_G;     // [4 nd][12 l][128 c]
    float* ob   = sm + FO_OB;    // [4 nd][12 l][64 d]
    float* rr   = sm + FO_RR;    // [48]
    float* bnp  = sm + FO_BNP;   // [512]

    int t = threadIdx.x;
    int n0 = blockIdx.x*4;
    int nd = t >> 6, u = t & 63;

    // ---- h row 0 (= hs) ----
    h[nd*(R9*DD) + u] = __ldg(&hs[(size_t)(n0 + nd)*DD + u]);

    // ---- gather (A+I) spmm: rows 1..8 = own mailbox + 8 src mailboxes ----
    // src indices read directly (uniform per 128-thread group -> L1 broadcast)
#pragma unroll
    for (int i = t; i < 4*128; i += 256) {
        int gn = i >> 7, idx = i & 127;
        float4 a4 = ((const float4*)(g_hflat + (size_t)(n0 + gn)*(KK*DD)))[idx];
#pragma unroll
        for (int k = 0; k < KK; k++) {
            int s = __ldg(&src[(n0 + gn)*KK + k]);
            float4 v = ((const float4*)(g_hflat + (size_t)s*(KK*DD)))[idx];
            a4.x += v.x; a4.y += v.y; a4.z += v.z; a4.w += v.w;
        }
        ((float4*)(h + gn*(R9*DD) + DD))[idx] = a4;
    }
    __syncthreads();

    // ---- fc1 (channels {2u,2u+1,128+2u,128+2u+1}) + in-register conv + gate ----
    {
        float acc[R9][4];
#pragma unroll
        for (int l = 0; l < R9; l++) { acc[l][0]=0; acc[l][1]=0; acc[l][2]=0; acc[l][3]=0; }
        const float* hrow = h + nd*(R9*DD);
#pragma unroll 2
        for (int k4 = 0; k4 < 16; k4++) {
            float4 w0 = *(const float4*)&g_w1q[(k4*4+0)*256 + 4*u];
            float4 w1 = *(const float4*)&g_w1q[(k4*4+1)*256 + 4*u];
            float4 w2 = *(const float4*)&g_w1q[(k4*4+2)*256 + 4*u];
            float4 w3 = *(const float4*)&g_w1q[(k4*4+3)*256 + 4*u];
#pragma unroll
            for (int l = 0; l < R9; l++) {
                float4 h4 = *(const float4*)&hrow[l*DD + k4*4];
                acc[l][0] += h4.x*w0.x + h4.y*w1.x + h4.z*w2.x + h4.w*w3.x;
                acc[l][1] += h4.x*w0.y + h4.y*w1.y + h4.z*w2.y + h4.w*w3.y;
                acc[l][2] += h4.x*w0.z + h4.y*w1.z + h4.z*w2.z + h4.w*w3.z;
                acc[l][3] += h4.x*w0.w + h4.y*w1.w + h4.z*w2.w + h4.w*w3.w;
            }
        }
        int c0 = 2*u, c1 = 2*u + 1;
        float b1x0 = __ldg(&fc1b[c0]),       b1x1 = __ldg(&fc1b[c1]);
        float b1z0 = __ldg(&fc1b[DIN + c0]), b1z1 = __ldg(&fc1b[DIN + c1]);
        float4 cwa = *(const float4*)&convw[c0*4];   // {w0,w1,w2,w3} ch c0
        float4 cwb = *(const float4*)&convw[c1*4];
        float cba = __ldg(&convb[c0]), cbb = __ldg(&convb[c1]);
        float* grow = gbuf + nd*(R12*DIN);
        float am1 = 0.f, am2 = 0.f, am3 = 0.f;   // history ch c0
        float bm1 = 0.f, bm2 = 0.f, bm3 = 0.f;   // history ch c1
#pragma unroll
        for (int l = 0; l < R12; l++) {
            float xa = (l <= 8) ? (acc[l][0] + b1x0) : b1x0;
            float xb = (l <= 8) ? (acc[l][1] + b1x1) : b1x1;
            float xca = cba + xa*cwa.w + am1*cwa.z + am2*cwa.y + am3*cwa.x;
            float xcb = cbb + xb*cwb.w + bm1*cwb.z + bm2*cwb.y + bm3*cwb.x;
            am3 = am2; am2 = am1; am1 = xa;
            bm3 = bm2; bm2 = bm1; bm1 = xb;
            float za = (l <= 8) ? (acc[l][2] + b1z0) : b1z0;
            float zb = (l <= 8) ? (acc[l][3] + b1z1) : b1z1;
            float2 gv;
            gv.x = xca*sigm(xca) * (za*sigm(za));
            gv.y = xcb*sigm(xcb) * (zb*sigm(zb));
            *(float2*)&grow[l*DIN + c0] = gv;
        }
    }
    __syncthreads();

    // ---- fc2: nd, d = u, all 12 rows ----
    {
        int d = u;
        float acc2[R12];
#pragma unroll
        for (int j = 0; j < R12; j++) acc2[j] = 0.f;
        const float* grow = gbuf + nd*(R12*DIN);
#pragma unroll 4
        for (int c4 = 0; c4 < 32; c4++) {
            float wa = __ldg(&g_w2t[(c4*4+0)*64 + d]);
            float wb = __ldg(&g_w2t[(c4*4+1)*64 + d]);
            float wc = __ldg(&g_w2t[(c4*4+2)*64 + d]);
            float wd = __ldg(&g_w2t[(c4*4+3)*64 + d]);
#pragma unroll
            for (int j = 0; j < R12; j++) {
                float4 g4 = *(const float4*)&grow[j*DIN + c4*4];
                acc2[j] += g4.x*wa + g4.y*wb + g4.z*wc + g4.w*wd;
            }
        }
        float b2 = __ldg(&fc2b[d]);
        float* obrow = ob + nd*(R12*DD);
#pragma unroll
        for (int j = 0; j < R12; j++) obrow[j*DD + d] = acc2[j] + b2;
    }
    __syncthreads();

    // ---- rms per row (48 rows, staggered reads) ----
    if (t < 4*R12) {
        int nn_ = t / R12, l = t % R12;
        const float* row = ob + nn_*(R12*DD) + l*DD;
        float s = 0.f;
#pragma unroll
        for (int dd = 0; dd < DD; dd++) { float v = row[(dd + t) & 63]; s += v*v; }
        rr[t] = rsqrtf(s * (1.f/DD) + EPS);
    }
    __syncthreads();

    // ---- y = rmsnorm*rms_w + h_input (rows>8: residual 0); BN partials ----
    {
        int d = u;
        float rw = __ldg(&rmsw[d]);
        float bsum = 0.f, bsq = 0.f;
        float* ydst = g_y + (size_t)(n0 + nd)*(R12*DD);
        const float* hrow = h + nd*(R9*DD);
        const float* obrow = ob + nd*(R12*DD);
#pragma unroll
        for (int l = 0; l < R12; l++) {
            float res = (l <= 8) ? hrow[l*DD + d] : 0.f;
            float v = obrow[l*DD + d] * rr[nd*R12 + l] * rw + res;
            ydst[l*DD + d] = v;
            bsum += v; bsq += v*v;
        }
        bnp[t] = bsum; bnp[256 + t] = bsq;
    }
    __syncthreads();
    if (t < DD) {
        atomicAdd(&g_bnsum[t], bnp[t] + bnp[t+64] + bnp[t+128] + bnp[t+192]);
    } else if (t < 2*DD) {
        int d = t - DD;
        atomicAdd(&g_bnsq[d], bnp[256+d] + bnp[256+d+64] + bnp[256+d+128] + bnp[256+d+192]);
    }
}

// ---------------- K5: BN apply + ReLU6 + L-agg (12 rows + constant tail) ----------------
__global__ void k5(const float* __restrict__ hs, const float* __restrict__ gamma,
                   const float* __restrict__ beta, const float* __restrict__ aggw,
                   const float* __restrict__ aggb, float* __restrict__ out) {
    int idx = blockIdx.x*256 + threadIdx.x;
    int d = idx & 63;
    float cnt = (float)(NN*LL);
    float yc = g_yc[d];
    float bs = g_bnsum[d] + 5.f*NN*yc;
    float bq = g_bnsq[d]  + 5.f*NN*yc*yc;
    float mean = bs / cnt;
    float var  = bq / cnt - mean*mean;
    float is = rsqrtf(var + EPS);
    float ga = __ldg(&gamma[d]) * is;
    float be = __ldg(&beta[d]) - mean * ga;
    const float* yrow = g_y + (size_t)(idx >> 6)*(R12*DD);
    float s = __ldg(&aggb[0]);
#pragma unroll
    for (int l = 0; l < R12; l++) {
        float v = yrow[l*DD + d] * ga + be;
        v = fminf(fmaxf(v, 0.f), 6.f);
        s += v * __ldg(&aggw[l]);
    }
    {
        float vc = fminf(fmaxf(yc * ga + be, 0.f), 6.f);
        float tailw = __ldg(&aggw[12]) + __ldg(&aggw[13]) + __ldg(&aggw[14])
                    + __ldg(&aggw[15]) + __ldg(&aggw[16]);
        s += vc * tailw;
    }
    out[idx] = s + hs[idx];
}

// ---------------- host ----------------
extern "C" void kernel_launch(void* const* d_in, const int* in_sizes, int n_in,
                              void* d_out, int out_size) {
    const float* hs     = (const float*)d_in[0];
    const float* hs_e   = (const float*)d_in[1];
    const float* degree = (const float*)d_in[2];
    const float* noise  = (const float*)d_in[3];
    const float* fc1w   = (const float*)d_in[4];
    const float* fc1b   = (const float*)d_in[5];
    const float* convw  = (const float*)d_in[6];
    const float* convb  = (const float*)d_in[7];
    const float* fc2w   = (const float*)d_in[8];
    const float* fc2b   = (const float*)d_in[9];
    const float* rmsw   = (const float*)d_in[10];
    const float* gamma  = (const float*)d_in[11];
    const float* beta   = (const float*)d_in[12];
    const float* aggw   = (const float*)d_in[13];
    const float* aggb   = (const float*)d_in[14];
    const int*   src    = (const int*)d_in[15];
    float* out = (float*)d_out;

    cudaFuncSetAttribute(k3, cudaFuncAttributeMaxDynamicSharedMemorySize, SMEM3);

    kwc<<<65, 256>>>(fc1w, fc2w, fc1b, convw, convb, fc2b, rmsw);
    k1<<<NN/4, 512>>>(hs, hs_e, degree, noise);
    k3<<<NN/4, 256, SMEM3>>>(hs, src, fc1b, convw, convb, fc2b, rmsw);
    k5<<<NN*DD/256, 256>>>(hs, gamma, beta, aggw, aggb, out);
}